// round 4
// baseline (speedup 1.0000x reference)
#include <cuda_runtime.h>

// Problem constants
#define B_    4
#define N_    512
#define T_    10
#define F_    516      // N + 4
#define HID   128
#define MSGD  32
#define UPDH  128
#define OUTD  4

// kB tiling
#define ITILE   8                   // i's per CTA
#define JSPLIT  4                   // j split across CTAs (blockIdx.z)
#define JCHUNK  (N_ / JSPLIT)       // 128 j per CTA
#define NWARP   8                   // warps per CTA = j-groups
#define JW      (JCHUNK / NWARP)    // 16 j per warp
#define KJ      2                   // j per staging round
#define RNDS    (JW / KJ)           // 8 rounds

// Scratch (static device arrays: no allocations allowed)
__device__ float g_C[B_ * N_ * HID];                 // C[b,j,hid], mb1 folded in
__device__ float g_part[JSPLIT * B_ * N_ * HID];     // partial H_sum per j-split

// ---------------------------------------------------------------------------
// packed fp32x2 helpers (sm_100+)
// ---------------------------------------------------------------------------
__device__ __forceinline__ float2 ffma2(float2 a, float2 b, float2 c) {
    float2 d;
    asm("fma.rn.f32x2 %0, %1, %2, %3;"
        : "=l"(reinterpret_cast<unsigned long long&>(d))
        : "l"(reinterpret_cast<unsigned long long&>(a)),
          "l"(reinterpret_cast<unsigned long long&>(b)),
          "l"(reinterpret_cast<unsigned long long&>(c)));
    return d;
}
__device__ __forceinline__ float2 fadd2(float2 a, float2 b) {
    float2 d;
    asm("add.rn.f32x2 %0, %1, %2;"
        : "=l"(reinterpret_cast<unsigned long long&>(d))
        : "l"(reinterpret_cast<unsigned long long&>(a)),
          "l"(reinterpret_cast<unsigned long long&>(b)));
    return d;
}

// ---------------------------------------------------------------------------
// Kernel A: C[b,j,hid] = mb1[hid] + sum_{t,k<4} x[b,j,t,k] * mW1[5t+k, hid]
// 512 blocks x 128 threads; weights in 40 regs; 4 (b,j) per block.
// ---------------------------------------------------------------------------
#define ABJ 4
__global__ __launch_bounds__(128) void kA(const float* __restrict__ x,
                                          const float* __restrict__ mW1,
                                          const float* __restrict__ mb1) {
    const int hid = threadIdx.x;
    float w[40];
#pragma unroll
    for (int r = 0; r < 40; ++r)
        w[r] = mW1[(5 * (r >> 2) + (r & 3)) * HID + hid];
    const float bias = mb1[hid];

    __shared__ float sb[ABJ][40];
    const int bj0 = blockIdx.x * ABJ;
    for (int idx = hid; idx < ABJ * 40; idx += 128) {
        const int nn = idx / 40, r = idx % 40;
        sb[nn][r] = x[((long)(bj0 + nn) * T_ + (r >> 2)) * F_ + (r & 3)];
    }
    __syncthreads();

    float acc[ABJ];
#pragma unroll
    for (int nn = 0; nn < ABJ; ++nn) acc[nn] = bias;
#pragma unroll
    for (int r = 0; r < 40; ++r) {
        const float wr = w[r];
#pragma unroll
        for (int nn = 0; nn < ABJ; ++nn) acc[nn] = fmaf(sb[nn][r], wr, acc[nn]);
    }
#pragma unroll
    for (int nn = 0; nn < ABJ; ++nn)
        g_C[(long)(bj0 + nn) * HID + hid] = acc[nn];
}

// ---------------------------------------------------------------------------
// Kernel B (dominant):
//   H_sum[b,i,:] = sum_j relu( C[b,j,:] + sum_t e[b,j,t,i] * w_t[:] )
// CTA = (itile of 8 i, b, j-quarter). 256 threads; warp = private j-group of
// 16 j, covering ALL 8 i x 128 hid. Lane owns 4 hids. f32x2 packed over i:
// acc {i,i+1}; weights duplicated {w,w} in 80 regs; each broadcast LDS.64
// e-pair feeds 4 FFMA2 (1:4 LDS:FMA). No CTA barriers in mainloop.
// ---------------------------------------------------------------------------
__global__ __launch_bounds__(256) void kB(const float* __restrict__ x,
                                          const float* __restrict__ mW1) {
    const int tid  = threadIdx.x;
    const int warp = tid >> 5, lane = tid & 31;
    const int itile = blockIdx.x;            // 0..63
    const int b     = blockIdx.y;            // 0..3
    const int js    = blockIdx.z;            // 0..3
    const int i0    = itile * ITILE;
    const int hid0  = lane * 4;              // 4 hids per lane

    // Duplicated weights {w,w}: 4 hid x 10 t (loop-invariant, 80 regs)
    float2 wd[T_][4];
#pragma unroll
    for (int t = 0; t < T_; ++t) {
        float4 wv = *reinterpret_cast<const float4*>(&mW1[(5 * t + 4) * HID + hid0]);
        wd[t][0] = make_float2(wv.x, wv.x);
        wd[t][1] = make_float2(wv.y, wv.y);
        wd[t][2] = make_float2(wv.z, wv.z);
        wd[t][3] = make_float2(wv.w, wv.w);
    }

    // Per-warp e staging: [warp][buf][jj][t][i]  (natural loader layout)
    __shared__ __align__(16) float e_s[NWARP][2][KJ][T_][ITILE];   // 10 KB
    __shared__ __align__(16) float red[NWARP][ITILE][HID];         // 32 KB

    const int  jbase = js * JCHUNK + warp * JW;
    const bool ldr   = (lane < 2 * T_);      // 20 loader lanes
    const int  lt    = lane >> 1;            // t
    const int  lhf   = lane & 1;             // i half
    const long estr  = (long)T_ * F_;

    const float* egp = x + ((long)(b * N_ + jbase) * T_ + lt) * F_ + 4 + i0 + lhf * 4;
    const float* cgp = g_C + (long)(b * N_ + jbase) * HID + hid0;

    float4 eH[KJ], cC[KJ], cH[KJ];

    // Prologue: stage round 0
    if (ldr) {
#pragma unroll
        for (int jj = 0; jj < KJ; ++jj)
            eH[jj] = *reinterpret_cast<const float4*>(egp + (long)jj * estr);
#pragma unroll
        for (int jj = 0; jj < KJ; ++jj)
            *reinterpret_cast<float4*>(&e_s[warp][0][jj][lt][lhf * 4]) = eH[jj];
    }
#pragma unroll
    for (int jj = 0; jj < KJ; ++jj)
        cC[jj] = *reinterpret_cast<const float4*>(cgp + (long)jj * HID);
    __syncwarp();

    float2 acc[4][4];   // [i-pair][hid]
#pragma unroll
    for (int ip = 0; ip < 4; ++ip)
#pragma unroll
        for (int h = 0; h < 4; ++h) acc[ip][h] = make_float2(0.f, 0.f);

#pragma unroll 1
    for (int r = 0; r < RNDS; ++r) {
        const int cur = r & 1;

        // depth-1 prefetch of round r+1
        if (r + 1 < RNDS) {
            const long jb = (long)(r + 1) * KJ;
            if (ldr) {
#pragma unroll
                for (int jj = 0; jj < KJ; ++jj)
                    eH[jj] = *reinterpret_cast<const float4*>(egp + (jb + jj) * estr);
            }
#pragma unroll
            for (int jj = 0; jj < KJ; ++jj)
                cH[jj] = *reinterpret_cast<const float4*>(cgp + (jb + jj) * HID);
        }

        // ---- compute round r: KJ j's x 8 i x 4 hid (x2 packed) ----
#pragma unroll
        for (int jj = 0; jj < KJ; ++jj) {
            const float2 cd0 = make_float2(cC[jj].x, cC[jj].x);
            const float2 cd1 = make_float2(cC[jj].y, cC[jj].y);
            const float2 cd2 = make_float2(cC[jj].z, cC[jj].z);
            const float2 cd3 = make_float2(cC[jj].w, cC[jj].w);
            const float* eb = &e_s[warp][cur][jj][0][0];
#pragma unroll
            for (int ip = 0; ip < 4; ++ip) {
                float2 p0 = cd0, p1 = cd1, p2 = cd2, p3 = cd3;
#pragma unroll
                for (int t = 0; t < T_; ++t) {
                    float2 e = *reinterpret_cast<const float2*>(eb + t * ITILE + 2 * ip);
                    p0 = ffma2(e, wd[t][0], p0);
                    p1 = ffma2(e, wd[t][1], p1);
                    p2 = ffma2(e, wd[t][2], p2);
                    p3 = ffma2(e, wd[t][3], p3);
                }
                acc[ip][0] = fadd2(acc[ip][0], make_float2(fmaxf(p0.x, 0.f), fmaxf(p0.y, 0.f)));
                acc[ip][1] = fadd2(acc[ip][1], make_float2(fmaxf(p1.x, 0.f), fmaxf(p1.y, 0.f)));
                acc[ip][2] = fadd2(acc[ip][2], make_float2(fmaxf(p2.x, 0.f), fmaxf(p2.y, 0.f)));
                acc[ip][3] = fadd2(acc[ip][3], make_float2(fmaxf(p3.x, 0.f), fmaxf(p3.y, 0.f)));
            }
        }

        __syncwarp();
        if (r + 1 < RNDS) {
            if (ldr) {
#pragma unroll
                for (int jj = 0; jj < KJ; ++jj)
                    *reinterpret_cast<float4*>(&e_s[warp][cur ^ 1][jj][lt][lhf * 4]) = eH[jj];
            }
#pragma unroll
            for (int jj = 0; jj < KJ; ++jj) cC[jj] = cH[jj];
        }
        __syncwarp();
    }

    // ---- epilogue: reduce the 8 j-group warps, store one slice ----
#pragma unroll
    for (int ip = 0; ip < 4; ++ip) {
#pragma unroll
        for (int h = 0; h < 4; ++h) {
            red[warp][2 * ip + 0][hid0 + h] = acc[ip][h].x;
            red[warp][2 * ip + 1][hid0 + h] = acc[ip][h].y;
        }
    }
    __syncthreads();

    {
        const int ii = tid >> 5;             // 0..7
        const int h4 = (tid & 31) * 4;       // 0..124
        float4 s = *reinterpret_cast<const float4*>(&red[0][ii][h4]);
#pragma unroll
        for (int g = 1; g < NWARP; ++g) {
            float4 v = *reinterpret_cast<const float4*>(&red[g][ii][h4]);
            s.x += v.x; s.y += v.y; s.z += v.z; s.w += v.w;
        }
        *reinterpret_cast<float4*>(
            &g_part[(long)js * (B_ * N_ * HID) + ((long)(b * N_ + i0 + ii)) * HID + h4]) = s;
    }
}

// ---------------------------------------------------------------------------
// Kernel C: per node — reduce j-split partials, apply mW2 (+ N*mb2),
// concat node_feat, 36 -> 128 (relu) -> 4 MLP. Block = 16 nodes, weights smem.
// ---------------------------------------------------------------------------
#define NPB 16
__global__ __launch_bounds__(128) void kC(const float* __restrict__ x,
                                          const float* __restrict__ mW2,
                                          const float* __restrict__ mb2,
                                          const float* __restrict__ iW1,
                                          const float* __restrict__ ib1,
                                          const float* __restrict__ iW2,
                                          const float* __restrict__ ib2,
                                          float* __restrict__ out) {
    const int tid = threadIdx.x;

    __shared__ float s_mW2[HID * MSGD];          // 16 KB
    __shared__ float s_iW1[(MSGD + 4) * UPDH];   // 18 KB
    __shared__ float s_iW2[UPDH * OUTD];         // 2 KB
    __shared__ float s_mb2[MSGD], s_ib1[UPDH], s_ib2[OUTD];
    __shared__ float s_h[HID];
    __shared__ float s_red[4][MSGD];
    __shared__ float s_mi[MSGD + 4];
    __shared__ float s_h2[UPDH];
    __shared__ float s_nf[NPB][4];

    for (int i = tid; i < HID * MSGD; i += 128)        s_mW2[i] = mW2[i];
    for (int i = tid; i < (MSGD + 4) * UPDH; i += 128) s_iW1[i] = iW1[i];
    for (int i = tid; i < UPDH * OUTD; i += 128)       s_iW2[i] = iW2[i];
    if (tid < MSGD) s_mb2[tid] = mb2[tid];
    s_ib1[tid] = ib1[tid];
    if (tid < OUTD) s_ib2[tid] = ib2[tid];
    if (tid < NPB * 4) {
        const int nn = tid >> 2, k = tid & 3;
        s_nf[nn][k] = x[((long)(blockIdx.x * NPB + nn) * T_ + (T_ - 1)) * F_ + k];
    }
    __syncthreads();

    for (int nn = 0; nn < NPB; ++nn) {
        const long node = (long)blockIdx.x * NPB + nn;

        float h = 0.f;
#pragma unroll
        for (int p = 0; p < JSPLIT; ++p)
            h += g_part[(long)p * (B_ * N_ * HID) + node * HID + tid];
        s_h[tid] = h;
        __syncthreads();

        {   // mW2 GEMV split 4 ways over k
            const int m = tid & 31, seg = tid >> 5;
            float a = 0.f;
#pragma unroll
            for (int k2 = 0; k2 < 32; ++k2) {
                const int k = seg * 32 + k2;
                a = fmaf(s_h[k], s_mW2[k * MSGD + m], a);
            }
            s_red[seg][m] = a;
        }
        __syncthreads();
        if (tid < MSGD)
            s_mi[tid] = s_red[0][tid] + s_red[1][tid] + s_red[2][tid] + s_red[3][tid]
                      + (float)N_ * s_mb2[tid];
        if (tid < 4) s_mi[MSGD + tid] = s_nf[nn][tid];
        __syncthreads();

        {   // 36 -> 128 relu
            float a = s_ib1[tid];
#pragma unroll
            for (int k = 0; k < MSGD + 4; ++k)
                a = fmaf(s_mi[k], s_iW1[k * UPDH + tid], a);
            s_h2[tid] = fmaxf(a, 0.f);
        }
        __syncthreads();

        {   // 128 -> 4: warp o computes output o, shuffle-reduce
            const int o = tid >> 5, lane = tid & 31;
            float a = 0.f;
#pragma unroll
            for (int kk = 0; kk < 4; ++kk) {
                const int k = lane + kk * 32;
                a = fmaf(s_h2[k], s_iW2[k * OUTD + o], a);
            }
#pragma unroll
            for (int off = 16; off; off >>= 1) a += __shfl_xor_sync(~0u, a, off);
            if (lane == 0) out[node * OUTD + o] = a + s_ib2[o];
        }
        __syncthreads();
    }
}

// ---------------------------------------------------------------------------
extern "C" void kernel_launch(void* const* d_in, const int* in_sizes, int n_in,
                              void* d_out, int out_size) {
    const float* x   = (const float*)d_in[0];
    const float* mW1 = (const float*)d_in[1];
    const float* mb1 = (const float*)d_in[2];
    const float* mW2 = (const float*)d_in[3];
    const float* mb2 = (const float*)d_in[4];
    const float* iW1 = (const float*)d_in[5];
    const float* ib1 = (const float*)d_in[6];
    const float* iW2 = (const float*)d_in[7];
    const float* ib2 = (const float*)d_in[8];
    float* out = (float*)d_out;

    kA<<<B_ * N_ / ABJ, HID>>>(x, mW1, mb1);          // 512 blocks

    dim3 gB(N_ / ITILE, B_, JSPLIT);                  // (64, 4, 4) = 1024 CTAs
    kB<<<gB, 256>>>(x, mW1);

    kC<<<B_ * N_ / NPB, HID>>>(x, mW2, mb2, iW1, ib1, iW2, ib2, out);
}

// round 5
// speedup vs baseline: 1.1435x; 1.1435x over previous
#include <cuda_runtime.h>

// Problem constants
#define B_    4
#define N_    512
#define T_    10
#define F_    516      // N + 4
#define HID   128
#define MSGD  32
#define UPDH  128
#define OUTD  4

// kB tiling
#define ITILE   8                   // i's per CTA
#define JSPLIT  8                   // j split across CTAs (blockIdx.z)
#define JCHUNK  (N_ / JSPLIT)       // 64 j per CTA
#define NWARP   4                   // warps per CTA = j-groups
#define JW      (JCHUNK / NWARP)    // 16 j per warp
#define KJ      2                   // j per staging round
#define RNDS    (JW / KJ)           // 8 rounds

// Scratch (static device arrays: no allocations allowed)
__device__ float g_C[B_ * N_ * HID];                 // C[b,j,hid], mb1 folded in
__device__ float g_part[JSPLIT * B_ * N_ * HID];     // partial H_sum per j-split

// ---------------------------------------------------------------------------
// packed fp32x2 helpers (sm_100+)
// ---------------------------------------------------------------------------
__device__ __forceinline__ float2 ffma2(float2 a, float2 b, float2 c) {
    float2 d;
    asm("fma.rn.f32x2 %0, %1, %2, %3;"
        : "=l"(reinterpret_cast<unsigned long long&>(d))
        : "l"(reinterpret_cast<unsigned long long&>(a)),
          "l"(reinterpret_cast<unsigned long long&>(b)),
          "l"(reinterpret_cast<unsigned long long&>(c)));
    return d;
}
__device__ __forceinline__ float2 fadd2(float2 a, float2 b) {
    float2 d;
    asm("add.rn.f32x2 %0, %1, %2;"
        : "=l"(reinterpret_cast<unsigned long long&>(d))
        : "l"(reinterpret_cast<unsigned long long&>(a)),
          "l"(reinterpret_cast<unsigned long long&>(b)));
    return d;
}

// ---------------------------------------------------------------------------
// Kernel A: C[b,j,hid] = mb1[hid] + sum_{t,k<4} x[b,j,t,k] * mW1[5t+k, hid]
// 1024 blocks x 128 threads; weights in 40 regs; 2 (b,j) per block.
// (measured-best config from round 3)
// ---------------------------------------------------------------------------
#define ABJ 2
__global__ __launch_bounds__(128) void kA(const float* __restrict__ x,
                                          const float* __restrict__ mW1,
                                          const float* __restrict__ mb1) {
    const int hid = threadIdx.x;
    float w[40];
#pragma unroll
    for (int r = 0; r < 40; ++r)
        w[r] = mW1[(5 * (r >> 2) + (r & 3)) * HID + hid];
    const float bias = mb1[hid];

    __shared__ float sb[ABJ][40];
    const int bj0 = blockIdx.x * ABJ;
    if (hid < ABJ * 40) {
        const int nn = hid / 40, r = hid % 40;
        sb[nn][r] = x[((long)(bj0 + nn) * T_ + (r >> 2)) * F_ + (r & 3)];
    }
    __syncthreads();

    float acc[ABJ];
#pragma unroll
    for (int nn = 0; nn < ABJ; ++nn) acc[nn] = bias;
#pragma unroll
    for (int r = 0; r < 40; ++r) {
        const float wr = w[r];
#pragma unroll
        for (int nn = 0; nn < ABJ; ++nn) acc[nn] = fmaf(sb[nn][r], wr, acc[nn]);
    }
#pragma unroll
    for (int nn = 0; nn < ABJ; ++nn)
        g_C[(long)(bj0 + nn) * HID + hid] = acc[nn];
}

// ---------------------------------------------------------------------------
// Kernel B (dominant):
//   H_sum[b,i,:] = sum_j relu( C[b,j,:] + sum_t e[b,j,t,i] * w_t[:] )
// CTA = (itile of 8 i, b, j-eighth). 128 threads / 4 warps; warp = private
// j-group of 16 j, covering ALL 8 i x 128 hid. Lane owns 4 hids. f32x2 packed
// over i: acc {i,i+1}; weights duplicated {w,w} in 80 regs; each broadcast
// LDS.64 e-pair feeds 4 FFMA2 (1:4). Small CTA -> 3 CTAs/SM (12 warps) at
// ~170 regs. No CTA barriers in mainloop.
// ---------------------------------------------------------------------------
__global__ __launch_bounds__(128, 3) void kB(const float* __restrict__ x,
                                             const float* __restrict__ mW1) {
    const int tid  = threadIdx.x;
    const int warp = tid >> 5, lane = tid & 31;
    const int itile = blockIdx.x;            // 0..63
    const int b     = blockIdx.y;            // 0..3
    const int js    = blockIdx.z;            // 0..7
    const int i0    = itile * ITILE;
    const int hid0  = lane * 4;              // 4 hids per lane

    // Duplicated weights {w,w}: 4 hid x 10 t (loop-invariant, 80 regs)
    float2 wd[T_][4];
#pragma unroll
    for (int t = 0; t < T_; ++t) {
        float4 wv = *reinterpret_cast<const float4*>(&mW1[(5 * t + 4) * HID + hid0]);
        wd[t][0] = make_float2(wv.x, wv.x);
        wd[t][1] = make_float2(wv.y, wv.y);
        wd[t][2] = make_float2(wv.z, wv.z);
        wd[t][3] = make_float2(wv.w, wv.w);
    }

    // Per-warp e staging: [warp][buf][jj][t][i]  (natural loader layout)
    __shared__ __align__(16) float e_s[NWARP][2][KJ][T_][ITILE];   // 5 KB
    __shared__ __align__(16) float red[NWARP][ITILE][HID];         // 16 KB

    const int  jbase = js * JCHUNK + warp * JW;
    const bool ldr   = (lane < 2 * T_);      // 20 loader lanes
    const int  lt    = lane >> 1;            // t
    const int  lhf   = lane & 1;             // i half
    const long estr  = (long)T_ * F_;

    const float* egp = x + ((long)(b * N_ + jbase) * T_ + lt) * F_ + 4 + i0 + lhf * 4;
    const float* cgp = g_C + (long)(b * N_ + jbase) * HID + hid0;

    float4 eH[KJ], cC[KJ], cH[KJ];

    // Prologue: stage round 0
    if (ldr) {
#pragma unroll
        for (int jj = 0; jj < KJ; ++jj)
            eH[jj] = *reinterpret_cast<const float4*>(egp + (long)jj * estr);
#pragma unroll
        for (int jj = 0; jj < KJ; ++jj)
            *reinterpret_cast<float4*>(&e_s[warp][0][jj][lt][lhf * 4]) = eH[jj];
    }
#pragma unroll
    for (int jj = 0; jj < KJ; ++jj)
        cC[jj] = *reinterpret_cast<const float4*>(cgp + (long)jj * HID);
    __syncwarp();

    float2 acc[4][4];   // [i-pair][hid]
#pragma unroll
    for (int ip = 0; ip < 4; ++ip)
#pragma unroll
        for (int h = 0; h < 4; ++h) acc[ip][h] = make_float2(0.f, 0.f);

#pragma unroll 1
    for (int r = 0; r < RNDS; ++r) {
        const int cur = r & 1;

        // depth-1 prefetch of round r+1
        if (r + 1 < RNDS) {
            const long jb = (long)(r + 1) * KJ;
            if (ldr) {
#pragma unroll
                for (int jj = 0; jj < KJ; ++jj)
                    eH[jj] = *reinterpret_cast<const float4*>(egp + (jb + jj) * estr);
            }
#pragma unroll
            for (int jj = 0; jj < KJ; ++jj)
                cH[jj] = *reinterpret_cast<const float4*>(cgp + (jb + jj) * HID);
        }

        // ---- compute round r: KJ j's x 8 i x 4 hid (x2 packed over i) ----
#pragma unroll
        for (int jj = 0; jj < KJ; ++jj) {
            const float2 cd0 = make_float2(cC[jj].x, cC[jj].x);
            const float2 cd1 = make_float2(cC[jj].y, cC[jj].y);
            const float2 cd2 = make_float2(cC[jj].z, cC[jj].z);
            const float2 cd3 = make_float2(cC[jj].w, cC[jj].w);
            const float* eb = &e_s[warp][cur][jj][0][0];
#pragma unroll
            for (int ip = 0; ip < 4; ++ip) {
                float2 p0 = cd0, p1 = cd1, p2 = cd2, p3 = cd3;
#pragma unroll
                for (int t = 0; t < T_; ++t) {
                    float2 e = *reinterpret_cast<const float2*>(eb + t * ITILE + 2 * ip);
                    p0 = ffma2(e, wd[t][0], p0);
                    p1 = ffma2(e, wd[t][1], p1);
                    p2 = ffma2(e, wd[t][2], p2);
                    p3 = ffma2(e, wd[t][3], p3);
                }
                acc[ip][0] = fadd2(acc[ip][0], make_float2(fmaxf(p0.x, 0.f), fmaxf(p0.y, 0.f)));
                acc[ip][1] = fadd2(acc[ip][1], make_float2(fmaxf(p1.x, 0.f), fmaxf(p1.y, 0.f)));
                acc[ip][2] = fadd2(acc[ip][2], make_float2(fmaxf(p2.x, 0.f), fmaxf(p2.y, 0.f)));
                acc[ip][3] = fadd2(acc[ip][3], make_float2(fmaxf(p3.x, 0.f), fmaxf(p3.y, 0.f)));
            }
        }

        __syncwarp();
        if (r + 1 < RNDS) {
            if (ldr) {
#pragma unroll
                for (int jj = 0; jj < KJ; ++jj)
                    *reinterpret_cast<float4*>(&e_s[warp][cur ^ 1][jj][lt][lhf * 4]) = eH[jj];
            }
#pragma unroll
            for (int jj = 0; jj < KJ; ++jj) cC[jj] = cH[jj];
        }
        __syncwarp();
    }

    // ---- epilogue: reduce the 4 j-group warps, store one slice ----
#pragma unroll
    for (int ip = 0; ip < 4; ++ip) {
#pragma unroll
        for (int h = 0; h < 4; ++h) {
            red[warp][2 * ip + 0][hid0 + h] = acc[ip][h].x;
            red[warp][2 * ip + 1][hid0 + h] = acc[ip][h].y;
        }
    }
    __syncthreads();

    {
        const int h4  = (tid & 31) * 4;      // 0..124
        const int ii0 = tid >> 5;            // 0..3 -> handles ii0 and ii0+4
#pragma unroll
        for (int q = 0; q < 2; ++q) {
            const int ii = ii0 + q * 4;
            float4 s = *reinterpret_cast<const float4*>(&red[0][ii][h4]);
#pragma unroll
            for (int g = 1; g < NWARP; ++g) {
                float4 v = *reinterpret_cast<const float4*>(&red[g][ii][h4]);
                s.x += v.x; s.y += v.y; s.z += v.z; s.w += v.w;
            }
            *reinterpret_cast<float4*>(
                &g_part[(long)js * (B_ * N_ * HID) + ((long)(b * N_ + i0 + ii)) * HID + h4]) = s;
        }
    }
}

// ---------------------------------------------------------------------------
// Kernel C: per node — reduce j-split partials, apply mW2 (+ N*mb2),
// concat node_feat, 36 -> 128 (relu) -> 4 MLP. Block = 16 nodes, weights smem.
// ---------------------------------------------------------------------------
#define NPB 16
__global__ __launch_bounds__(128) void kC(const float* __restrict__ x,
                                          const float* __restrict__ mW2,
                                          const float* __restrict__ mb2,
                                          const float* __restrict__ iW1,
                                          const float* __restrict__ ib1,
                                          const float* __restrict__ iW2,
                                          const float* __restrict__ ib2,
                                          float* __restrict__ out) {
    const int tid = threadIdx.x;

    __shared__ float s_mW2[HID * MSGD];          // 16 KB
    __shared__ float s_iW1[(MSGD + 4) * UPDH];   // 18 KB
    __shared__ float s_iW2[UPDH * OUTD];         // 2 KB
    __shared__ float s_mb2[MSGD], s_ib1[UPDH], s_ib2[OUTD];
    __shared__ float s_h[HID];
    __shared__ float s_red[4][MSGD];
    __shared__ float s_mi[MSGD + 4];
    __shared__ float s_h2[UPDH];
    __shared__ float s_nf[NPB][4];

    for (int i = tid; i < HID * MSGD; i += 128)        s_mW2[i] = mW2[i];
    for (int i = tid; i < (MSGD + 4) * UPDH; i += 128) s_iW1[i] = iW1[i];
    for (int i = tid; i < UPDH * OUTD; i += 128)       s_iW2[i] = iW2[i];
    if (tid < MSGD) s_mb2[tid] = mb2[tid];
    s_ib1[tid] = ib1[tid];
    if (tid < OUTD) s_ib2[tid] = ib2[tid];
    if (tid < NPB * 4) {
        const int nn = tid >> 2, k = tid & 3;
        s_nf[nn][k] = x[((long)(blockIdx.x * NPB + nn) * T_ + (T_ - 1)) * F_ + k];
    }
    __syncthreads();

    for (int nn = 0; nn < NPB; ++nn) {
        const long node = (long)blockIdx.x * NPB + nn;

        float h = 0.f;
#pragma unroll
        for (int p = 0; p < JSPLIT; ++p)
            h += g_part[(long)p * (B_ * N_ * HID) + node * HID + tid];
        s_h[tid] = h;
        __syncthreads();

        {   // mW2 GEMV split 4 ways over k
            const int m = tid & 31, seg = tid >> 5;
            float a = 0.f;
#pragma unroll
            for (int k2 = 0; k2 < 32; ++k2) {
                const int k = seg * 32 + k2;
                a = fmaf(s_h[k], s_mW2[k * MSGD + m], a);
            }
            s_red[seg][m] = a;
        }
        __syncthreads();
        if (tid < MSGD)
            s_mi[tid] = s_red[0][tid] + s_red[1][tid] + s_red[2][tid] + s_red[3][tid]
                      + (float)N_ * s_mb2[tid];
        if (tid < 4) s_mi[MSGD + tid] = s_nf[nn][tid];
        __syncthreads();

        {   // 36 -> 128 relu
            float a = s_ib1[tid];
#pragma unroll
            for (int k = 0; k < MSGD + 4; ++k)
                a = fmaf(s_mi[k], s_iW1[k * UPDH + tid], a);
            s_h2[tid] = fmaxf(a, 0.f);
        }
        __syncthreads();

        {   // 128 -> 4: warp o computes output o, shuffle-reduce
            const int o = tid >> 5, lane = tid & 31;
            float a = 0.f;
#pragma unroll
            for (int kk = 0; kk < 4; ++kk) {
                const int k = lane + kk * 32;
                a = fmaf(s_h2[k], s_iW2[k * OUTD + o], a);
            }
#pragma unroll
            for (int off = 16; off; off >>= 1) a += __shfl_xor_sync(~0u, a, off);
            if (lane == 0) out[node * OUTD + o] = a + s_ib2[o];
        }
        __syncthreads();
    }
}

// ---------------------------------------------------------------------------
extern "C" void kernel_launch(void* const* d_in, const int* in_sizes, int n_in,
                              void* d_out, int out_size) {
    const float* x   = (const float*)d_in[0];
    const float* mW1 = (const float*)d_in[1];
    const float* mb1 = (const float*)d_in[2];
    const float* mW2 = (const float*)d_in[3];
    const float* mb2 = (const float*)d_in[4];
    const float* iW1 = (const float*)d_in[5];
    const float* ib1 = (const float*)d_in[6];
    const float* iW2 = (const float*)d_in[7];
    const float* ib2 = (const float*)d_in[8];
    float* out = (float*)d_out;

    kA<<<B_ * N_ / ABJ, HID>>>(x, mW1, mb1);          // 1024 blocks

    dim3 gB(N_ / ITILE, B_, JSPLIT);                  // (64, 4, 8) = 2048 CTAs
    kB<<<gB, 128>>>(x, mW1);

    kC<<<B_ * N_ / NPB, HID>>>(x, mW2, mb2, iW1, ib1, iW2, ib2, out);
}